// round 3
// baseline (speedup 1.0000x reference)
#include <cuda_runtime.h>

// ---------------------------------------------------------------------------
// MomGRU persistent recurrence, round 3.
// 128 CTAs = 16 batch-blocks x 8 hidden-blocks; cluster(8) = the 8 hidden
// CTAs of one batch block. h is SMEM-resident (double buffer); each CTA
// PUSHES its computed h-slice into all 8 cluster CTAs via st.shared::cluster,
// synchronized by one smem mbarrier per CTA (count 8, parity per step).
// No global h, no barrier.cluster, no L2 round trip in the loop.
// ---------------------------------------------------------------------------

namespace {
constexpr int BATCH = 128;
constexpr int SEQ   = 1024;
constexpr int HID   = 256;
constexpr int GB    = 16;              // batch blocks
constexpr int GH    = 8;               // hidden blocks (= cluster size)
constexpr int NCTA  = GB * GH;         // 128
constexpr int BB    = BATCH / GB;      // 8 batches per CTA
constexpr int UPC   = HID / GH;        // 32 hidden units per CTA
constexpr int NROWS = 3 * UPC;         // 96 W_hh rows per CTA
constexpr int NTH   = 256;
constexpr int RSW   = HID + 16;        // 272 weight row stride (floats)
constexpr int RSH   = HID + 4;         // 260 h row stride (floats)
constexpr int HBSZ  = BB * RSH;        // 2080 floats per h buffer

// smem layout (floats)
constexpr int OFF_MBAR = 0;                      // 16B (mbarrier + pad)
constexpr int OFF_W    = 4;                      // NROWS * RSW
constexpr int OFF_HB   = OFF_W + NROWS * RSW;    // 2 * HBSZ (double buffer)
constexpr int OFF_WBH  = OFF_HB + 2 * HBSZ;      // HID
constexpr int OFF_WHD  = OFF_WBH + HID;          // HID
constexpr int OFF_BS   = OFF_WHD + HID;          // BB
constexpr int OFF_XS   = OFF_BS + BB;            // BB float2
constexpr int SMEM_FLOATS = OFF_XS + BB * 2;
constexpr int SMEM_BYTES  = SMEM_FLOATS * 4;     // ~120.4 KB
}

// ---- packed fp32x2 helpers -------------------------------------------------
__device__ __forceinline__ unsigned long long pk2(float2 v) {
    unsigned long long r;
    asm("mov.b64 %0, {%1,%2};" : "=l"(r) : "f"(v.x), "f"(v.y));
    return r;
}
__device__ __forceinline__ float2 upk2(unsigned long long v) {
    float2 r;
    asm("mov.b64 {%0,%1}, %2;" : "=f"(r.x), "=f"(r.y) : "l"(v));
    return r;
}
__device__ __forceinline__ float2 ffma2(float2 a, float2 b, float2 c) {
    unsigned long long d;
    asm("fma.rn.f32x2 %0, %1, %2, %3;"
        : "=l"(d) : "l"(pk2(a)), "l"(pk2(b)), "l"(pk2(c)));
    return upk2(d);
}

__device__ __forceinline__ float sigf(float x) {
    return __fdividef(1.0f, 1.0f + __expf(-x));
}
__device__ __forceinline__ float tanh_fast(float x) {
    float ax = fabsf(x);
    float e  = __expf(-2.0f * ax);
    return copysignf(__fdividef(1.0f - e, 1.0f + e), x);
}

__device__ __forceinline__ unsigned smem_u32(const void* p) {
    unsigned a;
    asm("{ .reg .u64 t; cvta.to.shared.u64 t, %1; cvt.u32.u64 %0, t; }"
        : "=r"(a) : "l"(p));
    return a;
}
__device__ __forceinline__ unsigned mapa_rank(unsigned local, unsigned rank) {
    unsigned r;
    asm("mapa.shared::cluster.u32 %0, %1, %2;" : "=r"(r) : "r"(local), "r"(rank));
    return r;
}
__device__ __forceinline__ void st_cluster_f32(unsigned addr, float v) {
    asm volatile("st.shared::cluster.f32 [%0], %1;" :: "r"(addr), "f"(v) : "memory");
}
__device__ __forceinline__ void mbar_init(unsigned mbar, unsigned cnt) {
    asm volatile("mbarrier.init.shared.b64 [%0], %1;" :: "r"(mbar), "r"(cnt) : "memory");
}
__device__ __forceinline__ void mbar_arrive_peer(unsigned local_mbar, unsigned rank) {
    asm volatile(
        "{\n\t.reg .b32 r;\n\t"
        "mapa.shared::cluster.u32 r, %0, %1;\n\t"
        "mbarrier.arrive.release.cluster.shared::cluster.b64 _, [r];\n\t}"
        :: "r"(local_mbar), "r"(rank) : "memory");
}
__device__ __forceinline__ void mbar_wait(unsigned mbar, unsigned parity) {
    unsigned done;
    asm volatile(
        "{\n\t.reg .pred p;\n\t"
        "mbarrier.try_wait.parity.acquire.cluster.shared::cta.b64 p, [%1], %2;\n\t"
        "selp.b32 %0, 1, 0, p;\n\t}"
        : "=r"(done) : "r"(mbar), "r"(parity) : "memory");
    if (!done) {
        asm volatile(
            "{\n\t.reg .pred P1;\n\t"
            "WL_%=:\n\t"
            "mbarrier.try_wait.parity.acquire.cluster.shared::cta.b64 P1, [%0], %1, 0x989680;\n\t"
            "@P1 bra.uni WD_%=;\n\t"
            "bra.uni WL_%=;\n\t"
            "WD_%=:\n\t}"
            :: "r"(mbar), "r"(parity) : "memory");
    }
}
#define CLUSTER_SYNC_() do {                                          \
    asm volatile("barrier.cluster.arrive.aligned;" ::: "memory");     \
    asm volatile("barrier.cluster.wait.aligned;"   ::: "memory");     \
} while (0)

extern "C" __global__ void __launch_bounds__(NTH, 1) __cluster_dims__(GH, 1, 1)
momgru_kernel(const float* __restrict__ x,
              const float* __restrict__ W_ih,
              const float* __restrict__ W_hh,
              const float* __restrict__ b_ih,
              const float* __restrict__ b_hh,
              const float* __restrict__ Wb_x,
              const float* __restrict__ Wb_h,
              const float* __restrict__ b_beta,
              const float* __restrict__ s_ptr,
              const float* __restrict__ W_head,
              const float* __restrict__ b_head,
              float* __restrict__ out)
{
    extern __shared__ float sm[];
    float*  ws     = sm + OFF_W;
    float*  hb     = sm + OFF_HB;       // [2][BB][RSH]
    float*  wbhs   = sm + OFF_WBH;
    float*  whds   = sm + OFF_WHD;
    float*  beta_s = sm + OFF_BS;
    float2* xs     = (float2*)(sm + OFF_XS);

    const unsigned sbase = smem_u32(sm);
    const unsigned mbar  = sbase + OFF_MBAR * 4;

    const int tid = threadIdx.x;
    const int j   = blockIdx.x & (GH - 1);    // hidden block / cluster rank
    const int i   = blockIdx.x >> 3;          // batch block
    const int b0  = i * BB;
    const int u0  = j * UPC;

    const int u  = tid >> 3;        // 0..31  hidden unit (local)
    const int bq = (tid >> 2) & 1;  // 0..1   batch quad
    const int ks = tid & 3;         // 0..3   K-split lane
    const int bg = bq * 4 + ks;     // 0..7   this thread's gate-owned batch

    // ---- one-time preload ----------------------------------------------------
    for (int e = tid; e < NROWS * HID; e += NTH) {
        int row = e >> 8;
        int k   = e & (HID - 1);
        int g   = row >> 5;
        int uu  = row & 31;
        ws[row * RSW + k] = W_hh[(g * HID + u0 + uu) * HID + k];
    }
    for (int e = tid; e < HID; e += NTH) {
        wbhs[e] = Wb_h[e];
        whds[e] = W_head[e];
    }
    // zero h buffer 0 (h0 = 0); buffer 1 fully written by step 0 pushes
    for (int e = tid; e < HBSZ; e += NTH) hb[e] = 0.0f;

    const float wbx0  = __ldg(Wb_x);
    const float wbx1  = __ldg(Wb_x + 1);
    const float bbeta = __ldg(b_beta);
    const float sv    = __ldg(s_ptr);
    const float bhead = __ldg(b_head);

    float2 wihg[3];
    float  bihg[3], bhhg[3];
    #pragma unroll
    for (int g = 0; g < 3; ++g) {
        int gr  = g * HID + u0 + u;
        wihg[g] = make_float2(__ldg(W_ih + gr * 2), __ldg(W_ih + gr * 2 + 1));
        bihg[g] = __ldg(b_ih + gr);
        bhhg[g] = __ldg(b_hh + gr);
    }

    if (tid == 0) mbar_init(mbar, GH);   // 8 arrivals per phase (1 per CTA)
    __syncthreads();
    CLUSTER_SYNC_();   // peers' mbarrier init + h0 zero done before any push

    // precompute the 8 remote h-buffer base addresses for this thread's slot
    const unsigned slot = (unsigned)(bg * RSH + u0 + u) * 4u;
    unsigned peer_hb[GH];
    #pragma unroll
    for (int p = 0; p < GH; ++p)
        peer_hb[p] = mapa_rank(sbase + OFF_HB * 4, (unsigned)p) + slot;

    // per-thread momentum state for (u, bg)
    float v0 = 0.f, v1 = 0.f, v2 = 0.f;

    const float* w0p = ws + (0 * UPC + u) * RSW + ks * 4;
    const float* w1p = ws + (1 * UPC + u) * RSW + ks * 4;
    const float* w2p = ws + (2 * UPC + u) * RSW + ks * 4;

    unsigned ph = 0;

    for (int t = 0; t < SEQ; ++t) {
        if (t > 0) { mbar_wait(mbar, ph); ph ^= 1; }   // acquire: h_t pushed into hb

        const float* hsb = hb + (t & 1) * HBSZ;

        // prefetch x (one lane per batch)
        float2 xv = make_float2(0.f, 0.f);
        const int bb = tid >> 3;     // beta batch (tid<64)
        const int kc = tid & 7;      // beta K-chunk lane
        if (tid < 64 && kc == 0)
            xv = __ldg((const float2*)x + (b0 + bb) * SEQ + t);

        // ---- beta: h . Wb_h (warps 0-1; 8 batches x 8 k-chunks) --------------
        if (tid < 64) {
            const float* hrow = hsb + bb * RSH + kc * 4;
            const float* wrow = wbhs + kc * 4;
            float2 a2 = make_float2(0.f, 0.f);
            #pragma unroll
            for (int kk = 0; kk < 8; ++kk) {
                float4 h4 = *(const float4*)(hrow + kk * 32);
                float4 w4 = *(const float4*)(wrow + kk * 32);
                a2 = ffma2(make_float2(w4.x, w4.y), make_float2(h4.x, h4.y), a2);
                a2 = ffma2(make_float2(w4.z, w4.w), make_float2(h4.z, h4.w), a2);
            }
            float a = a2.x + a2.y;
            a += __shfl_xor_sync(0xffffffffu, a, 1);
            a += __shfl_xor_sync(0xffffffffu, a, 2);
            a += __shfl_xor_sync(0xffffffffu, a, 4);
            if (kc == 0) {
                float bval = sigf(xv.x * wbx0 + xv.y * wbx1 + a + bbeta);
                beta_s[bb] = bval;
                xs[bb]     = xv;
                if (j == 0) out[BATCH + (b0 + bb) * SEQ + t] = bval;
            }
        }

        // ---- gh = h @ W_hh^T : f32x2 over K, per-thread (3 gates x 4 b) ------
        const float* h0p = hsb + (bq * 4 + 0) * RSH + ks * 4;
        const float* h1p = hsb + (bq * 4 + 1) * RSH + ks * 4;
        const float* h2p = hsb + (bq * 4 + 2) * RSH + ks * 4;
        const float* h3p = hsb + (bq * 4 + 3) * RSH + ks * 4;

        float2 acc[3][4];
        #pragma unroll
        for (int g = 0; g < 3; ++g)
            #pragma unroll
            for (int bi = 0; bi < 4; ++bi) acc[g][bi] = make_float2(0.f, 0.f);

        #pragma unroll
        for (int kk = 0; kk < 16; ++kk) {
            const int o = kk * 16;
            float4 w4[3], h4[4];
            w4[0] = *(const float4*)(w0p + o);
            w4[1] = *(const float4*)(w1p + o);
            w4[2] = *(const float4*)(w2p + o);
            h4[0] = *(const float4*)(h0p + o);
            h4[1] = *(const float4*)(h1p + o);
            h4[2] = *(const float4*)(h2p + o);
            h4[3] = *(const float4*)(h3p + o);
            #pragma unroll
            for (int g = 0; g < 3; ++g)
                #pragma unroll
                for (int bi = 0; bi < 4; ++bi)
                    acc[g][bi] = ffma2(make_float2(w4[g].x, w4[g].y),
                                       make_float2(h4[bi].x, h4[bi].y), acc[g][bi]);
            #pragma unroll
            for (int g = 0; g < 3; ++g)
                #pragma unroll
                for (int bi = 0; bi < 4; ++bi)
                    acc[g][bi] = ffma2(make_float2(w4[g].z, w4[g].w),
                                       make_float2(h4[bi].z, h4[bi].w), acc[g][bi]);
        }

        // ---- K-split reduce (bfly over ks lanes) -----------------------------
        float gsum[3][4];
        #pragma unroll
        for (int g = 0; g < 3; ++g)
            #pragma unroll
            for (int bi = 0; bi < 4; ++bi) {
                float sc = acc[g][bi].x + acc[g][bi].y;
                sc += __shfl_xor_sync(0xffffffffu, sc, 1);
                sc += __shfl_xor_sync(0xffffffffu, sc, 2);
                gsum[g][bi] = sc;
            }

        __syncthreads();   // beta_s / xs published

        // ---- v update + gates: thread owns (u, batch bg) ---------------------
        float hn;
        {
            const float  be    = beta_s[bg];
            const float2 xv2   = xs[bg];
            const float  hprev = hsb[bg * RSH + u0 + u];

            float pr = xv2.x * wihg[0].x + xv2.y * wihg[0].y + bihg[0];
            float pz = xv2.x * wihg[1].x + xv2.y * wihg[1].y + bihg[1];
            float pn = xv2.x * wihg[2].x + xv2.y * wihg[2].y + bihg[2];
            v0 = be * v0 + sv * pr;
            v1 = be * v1 + sv * pz;
            v2 = be * v2 + sv * pn;

            float ghr = gsum[0][ks] + bhhg[0];
            float ghz = gsum[1][ks] + bhhg[1];
            float ghn = gsum[2][ks] + bhhg[2];

            float r = sigf(v0 + ghr);
            float z = sigf(v1 + ghz);
            float n = tanh_fast(v2 + r * ghn);
            hn = (1.0f - z) * n + z * hprev;
        }

        // ---- push h_{t+1}(u0+u, bg) to all cluster CTAs (incl. self) ---------
        const unsigned boff = (unsigned)(((t + 1) & 1) * HBSZ) * 4u;
        #pragma unroll
        for (int p = 0; p < GH; ++p)
            st_cluster_f32(peer_hb[p] + boff, hn);

        __syncthreads();   // all pushes issued before the CTA's arrives
        if (tid < GH) {
            asm volatile("fence.acq_rel.cluster;" ::: "memory");
            mbar_arrive_peer(mbar, (unsigned)tid);
        }
    }

    mbar_wait(mbar, ph);   // final h_T (buffer 0) resident in local smem

    // ---- head: out[b] = h_T . W_head + b_head (rank-0 CTA per batch block) ---
    if (j == 0 && tid < 64) {
        int b  = tid >> 3;
        int kc = tid & 7;
        const float* hT = hb + b * RSH;          // buffer 0
        float2 a2 = make_float2(0.f, 0.f);
        #pragma unroll
        for (int kk = 0; kk < 8; ++kk) {
            float4 h4 = *(const float4*)(hT + kc * 4 + kk * 32);
            float4 w4 = *(const float4*)(whds + kc * 4 + kk * 32);
            a2 = ffma2(make_float2(w4.x, w4.y), make_float2(h4.x, h4.y), a2);
            a2 = ffma2(make_float2(w4.z, w4.w), make_float2(h4.z, h4.w), a2);
        }
        float a = a2.x + a2.y;
        a += __shfl_xor_sync(0xffffffffu, a, 1);
        a += __shfl_xor_sync(0xffffffffu, a, 2);
        a += __shfl_xor_sync(0xffffffffu, a, 4);
        if (kc == 0) out[b0 + b] = a + bhead;
    }

    CLUSTER_SYNC_();   // no CTA exits while peers may still read/receive
}

extern "C" void kernel_launch(void* const* d_in, const int* in_sizes, int n_in,
                              void* d_out, int out_size) {
    const float* x      = (const float*)d_in[0];
    const float* W_ih   = (const float*)d_in[1];
    const float* W_hh   = (const float*)d_in[2];
    const float* b_ih   = (const float*)d_in[3];
    const float* b_hh   = (const float*)d_in[4];
    const float* Wb_x   = (const float*)d_in[5];
    const float* Wb_h   = (const float*)d_in[6];
    const float* b_beta = (const float*)d_in[7];
    const float* s      = (const float*)d_in[8];
    const float* W_head = (const float*)d_in[9];
    const float* b_head = (const float*)d_in[10];

    cudaFuncSetAttribute(momgru_kernel,
                         cudaFuncAttributeMaxDynamicSharedMemorySize,
                         SMEM_BYTES);

    momgru_kernel<<<NCTA, NTH, SMEM_BYTES>>>(
        x, W_ih, W_hh, b_ih, b_hh, Wb_x, Wb_h, b_beta, s, W_head, b_head,
        (float*)d_out);
}